// round 4
// baseline (speedup 1.0000x reference)
#include <cuda_runtime.h>
#include <cuda_fp16.h>
#include <cstdint>
#include <cstddef>

// ---------------- Problem dims ----------------
#define N_ROWS 8192
#define D_IN   4096
#define D_OUT  4096

// ---------------- GEMM tiling -----------------
#define TM 128
#define TN 256
#define TK 64
#define M_TILES 64      // 8192/128
#define N_TILES 16      // 4096/256
#define K_ITERS 128     // (2*4096)/64 : Xh stages [0,64), Xl stages [64,128)
#define A_STAGE 16384   // TM*TK*2 bytes (fp16)
#define B_STAGE 32768   // TN*TK*2 bytes (fp16)
#define STAGE_BYTES 49152
#define NSTAGE 3
#define SMEM_DYN 148480 // 3*49152 + 1024 alignment slack

// Pre-swizzled, tile-ordered operand images (scratch via __device__ globals).
__device__ __align__(1024) uint8_t g_A[(size_t)M_TILES * K_ITERS * A_STAGE]; // 128 MB
__device__ __align__(1024) uint8_t g_B[(size_t)N_TILES * 64 * B_STAGE];      //  32 MB

// ---------------- helpers ----------------
static __device__ __forceinline__ uint32_t smem_u32(const void* p) {
    uint32_t a;
    asm("{ .reg .u64 t; cvta.to.shared.u64 t, %1; cvt.u32.u64 %0, t; }"
        : "=r"(a) : "l"(p));
    return a;
}

static __device__ __forceinline__ void cp16(uint32_t dst, const void* src) {
    asm volatile("cp.async.cg.shared.global [%0], [%1], 16;"
                 :: "r"(dst), "l"(src) : "memory");
}

static __device__ __forceinline__ void ldsm4(uint32_t (&r)[4], uint32_t addr) {
    asm volatile("ldmatrix.sync.aligned.m8n8.x4.shared.b16 {%0,%1,%2,%3}, [%4];"
                 : "=r"(r[0]), "=r"(r[1]), "=r"(r[2]), "=r"(r[3]) : "r"(addr));
}

static __device__ __forceinline__ void mma16816(float* d, const uint32_t* a,
                                                uint32_t b0, uint32_t b1) {
    asm volatile(
        "mma.sync.aligned.m16n8k16.row.col.f32.f16.f16.f32 "
        "{%0,%1,%2,%3}, {%4,%5,%6,%7}, {%8,%9}, {%0,%1,%2,%3};"
        : "+f"(d[0]), "+f"(d[1]), "+f"(d[2]), "+f"(d[3])
        : "r"(a[0]), "r"(a[1]), "r"(a[2]), "r"(a[3]), "r"(b0), "r"(b1));
}

// ============================================================================
// Prep X: split fp32 X into fp16 (hi, lo) images, pre-swizzled & tile-ordered.
// One thread = 8 consecutive K elements (one 16B swizzle chunk).
// ============================================================================
__global__ void prep_x_kernel(const float* __restrict__ X) {
    int g  = blockIdx.x * 256 + threadIdx.x;   // 8192*512 chunks
    int n  = g >> 9;
    int k0 = (g & 511) << 3;
    const float4* xp = reinterpret_cast<const float4*>(X + (size_t)n * D_IN + k0);
    float4 a = xp[0], b = xp[1];
    float xs[8] = {a.x, a.y, a.z, a.w, b.x, b.y, b.z, b.w};
    union { __half h[8]; uint4 u; } hi, lo;
#pragma unroll
    for (int j = 0; j < 8; j++) {
        __half h = __float2half_rn(xs[j]);
        hi.h[j] = h;
        lo.h[j] = __float2half_rn(xs[j] - __half2float(h));
    }
    int mt = n >> 7, m = n & 127, ks = k0 >> 6, kk = k0 & 63;
    uint32_t off = (uint32_t)(m * 128 + kk * 2);
    uint32_t sw  = off ^ ((off >> 3) & 0x70u);
    *reinterpret_cast<uint4*>(g_A + (size_t)(mt * 128 + ks)      * A_STAGE + sw) = hi.u;
    *reinterpret_cast<uint4*>(g_A + (size_t)(mt * 128 + ks + 64) * A_STAGE + sw) = lo.u;
}

// ============================================================================
// Prep W: W' = (W_nf4 * c1) * c_kbit2 + L1@L2, transposed to N-major [d][k],
// fp16, pre-swizzled & tile-ordered. Block tile: 64 k x 32 d.
// ============================================================================
__global__ void prep_w_kernel(const float* __restrict__ Wn, const float* __restrict__ c1p,
                              const float* __restrict__ ck, const float* __restrict__ L1,
                              const float* __restrict__ L2) {
    __shared__ float sL1[64 * 16];
    __shared__ float sL2[16 * 32];
    __shared__ __align__(16) __half sOut[32 * 64];
    const int t  = threadIdx.x;
    const int k0 = blockIdx.y * 64;
    const int d0 = blockIdx.x * 32;
    const float c1 = __ldg(c1p);

    for (int i = t; i < 1024; i += 256) sL1[i] = L1[(size_t)k0 * 16 + i];
    for (int i = t; i < 512;  i += 256) sL2[i] = L2[(size_t)(i >> 5) * D_OUT + d0 + (i & 31)];

    const int dd = t & 31;
    float wv[8];
#pragma unroll
    for (int i = 0; i < 8; i++) {
        int k = (t >> 5) + i * 8;
        size_t gi = (size_t)(k0 + k) * D_OUT + d0 + dd;
        wv[i] = (Wn[gi] * c1) * ck[gi];   // match reference mul order
    }
    __syncthreads();
#pragma unroll
    for (int i = 0; i < 8; i++) {
        int k = (t >> 5) + i * 8;
        float acc = wv[i];
#pragma unroll
        for (int r = 0; r < 16; r++) acc += sL1[k * 16 + r] * sL2[r * 32 + dd];
        sOut[dd * 64 + k] = __float2half_rn(acc);
    }
    __syncthreads();
    const int od = t >> 3, c = t & 7;
    uint4 v = *reinterpret_cast<uint4*>(&sOut[od * 64 + c * 8]);
    int ntile = blockIdx.x >> 3;
    int nloc  = ((blockIdx.x & 7) << 5) + od;
    uint32_t off = (uint32_t)(nloc * 128 + c * 16);
    uint32_t sw  = off ^ ((off >> 3) & 0x70u);
    *reinterpret_cast<uint4*>(g_B + (size_t)(ntile * 64 + blockIdx.y) * B_STAGE + sw) = v;
}

// ============================================================================
// GEMM: Y[8192,4096] = [Xh‖Xl] @ [W';W'] via mma.sync.m16n8k16 (HMMA).
// CTA tile 128x256, warp grid 2(m)x4(n) of 64x64 warp tiles.
// K-stage 64, 3-stage cp.async pipeline, SW128-swizzled smem + ldmatrix.
// ============================================================================
static __device__ __forceinline__ void load_stage(uint32_t sA, uint32_t sB,
                                                  const uint8_t* gA, const uint8_t* gB,
                                                  int tid) {
#pragma unroll
    for (int i = 0; i < 4; i++) {
        uint32_t o = (uint32_t)(tid + i * 256) * 16u;
        cp16(sA + o, gA + o);
    }
#pragma unroll
    for (int i = 0; i < 8; i++) {
        uint32_t o = (uint32_t)(tid + i * 256) * 16u;
        cp16(sB + o, gB + o);
    }
}

__global__ void __launch_bounds__(256, 1) qlora_gemm(float* __restrict__ Y) {
    extern __shared__ __align__(16) uint8_t smem[];
    const int tid  = threadIdx.x;
    const int wid  = tid >> 5;
    const int lane = tid & 31;
    const int nt = blockIdx.x;     // n-tile fastest -> W' stays L2-resident
    const int mt = blockIdx.y;

    const int wm = wid >> 2;       // 0..1
    const int wn = wid & 3;        // 0..3

    uint32_t base   = smem_u32(smem);
    uint32_t stage0 = (base + 1023u) & ~1023u;

    // Per-lane ldmatrix addressing invariants.
    // SW128 within a 128B-row tile reduces to: addr = row*128 + (kb ^ ((row&7)*16)).
    const int lr = lane & 15;              // row within 16-row fragment group
    const int lk = (lane >> 4) * 16;       // +8 halves for upper 16 lanes
    const int xm = (lr & 7) * 16;
    uint32_t aRowOff[4], bRowOff[4];
#pragma unroll
    for (int mi = 0; mi < 4; mi++) aRowOff[mi] = (uint32_t)((wm * 64 + mi * 16 + lr) * 128);
#pragma unroll
    for (int nj = 0; nj < 4; nj++) bRowOff[nj] = (uint32_t)((wn * 64 + nj * 16 + lr) * 128);

    float acc[4][8][4];
#pragma unroll
    for (int mi = 0; mi < 4; mi++)
#pragma unroll
        for (int nj = 0; nj < 8; nj++)
#pragma unroll
            for (int c = 0; c < 4; c++) acc[mi][nj][c] = 0.0f;

    // prologue: fill 3 stages
#pragma unroll
    for (int s = 0; s < NSTAGE; s++) {
        const uint8_t* gA = g_A + (size_t)(mt * 128 + s) * A_STAGE;
        const uint8_t* gB = g_B + (size_t)(nt * 64 + s) * B_STAGE;
        uint32_t sA = stage0 + s * STAGE_BYTES;
        load_stage(sA, sA + A_STAGE, gA, gB, tid);
        asm volatile("cp.async.commit_group;" ::: "memory");
    }

    int buf = 0;
    for (int it = 0; it < K_ITERS; ++it) {
        uint32_t sA = stage0 + buf * STAGE_BYTES;
        uint32_t sB = sA + A_STAGE;
        asm volatile("cp.async.wait_group 2;" ::: "memory");
        __syncthreads();

#pragma unroll
        for (int ks = 0; ks < 4; ks++) {
            uint32_t kb = (uint32_t)((ks * 32 + lk) ^ xm);
            uint32_t a[4][4], bq[4][4];
#pragma unroll
            for (int mi = 0; mi < 4; mi++) ldsm4(a[mi],  sA + aRowOff[mi] + kb);
#pragma unroll
            for (int nj = 0; nj < 4; nj++) ldsm4(bq[nj], sB + bRowOff[nj] + kb);
#pragma unroll
            for (int mi = 0; mi < 4; mi++)
#pragma unroll
                for (int nj = 0; nj < 4; nj++) {
                    mma16816(acc[mi][2 * nj],     a[mi], bq[nj][0], bq[nj][2]);
                    mma16816(acc[mi][2 * nj + 1], a[mi], bq[nj][1], bq[nj][3]);
                }
        }

        __syncthreads();      // all warps done reading buf before refill
        int nx = it + NSTAGE;
        if (nx < K_ITERS) {
            const uint8_t* gA = g_A + (size_t)(mt * 128 + nx) * A_STAGE;
            const uint8_t* gB = g_B + (size_t)(nt * 64 + (nx & 63)) * B_STAGE;
            load_stage(sA, sB, gA, gB, tid);
        }
        asm volatile("cp.async.commit_group;" ::: "memory");
        buf++; if (buf == NSTAGE) buf = 0;
    }

    // epilogue: direct fp32 stores (float2, 32B-sector aligned per lane quad)
    float* yBase = Y + (size_t)(mt * 128 + wm * 64) * D_OUT + nt * 256 + wn * 64;
    const int qr = lane >> 2;          // 0..7
    const int qc = (lane & 3) * 2;
#pragma unroll
    for (int mi = 0; mi < 4; mi++) {
        float* y0 = yBase + (size_t)(mi * 16 + qr) * D_OUT + qc;
        float* y1 = y0 + (size_t)8 * D_OUT;
#pragma unroll
        for (int nj = 0; nj < 8; nj++) {
            *reinterpret_cast<float2*>(y0 + nj * 8) = make_float2(acc[mi][nj][0], acc[mi][nj][1]);
            *reinterpret_cast<float2*>(y1 + nj * 8) = make_float2(acc[mi][nj][2], acc[mi][nj][3]);
        }
    }
}

// ============================================================================
extern "C" void kernel_launch(void* const* d_in, const int* in_sizes, int n_in,
                              void* d_out, int out_size) {
    (void)in_sizes; (void)n_in; (void)out_size;
    const float* X  = (const float*)d_in[0];
    const float* Wn = (const float*)d_in[1];
    const float* c1 = (const float*)d_in[2];
    const float* ck = (const float*)d_in[3];
    const float* L1 = (const float*)d_in[4];
    const float* L2 = (const float*)d_in[5];
    float* Y = (float*)d_out;

    prep_x_kernel<<<16384, 256>>>(X);
    prep_w_kernel<<<dim3(128, 64), 256>>>(Wn, c1, ck, L1, L2);
    cudaFuncSetAttribute(qlora_gemm, cudaFuncAttributeMaxDynamicSharedMemorySize, SMEM_DYN);
    qlora_gemm<<<dim3(N_TILES, M_TILES), 256, SMEM_DYN>>>(Y);
}

// round 5
// speedup vs baseline: 1.8349x; 1.8349x over previous
#include <cuda_runtime.h>
#include <cuda_fp16.h>
#include <cstdint>
#include <cstddef>

// ---------------- Problem dims ----------------
#define N_ROWS 8192
#define D_IN   4096
#define D_OUT  4096

// ---------------- GEMM tiling -----------------
#define TM 128
#define TN 256
#define TK 64
#define M_TILES 64      // 8192/128
#define N_TILES 16      // 4096/256
#define K_ITERS 64      // 4096/64 (single fp16 X image)
#define A_STAGE 16384   // TM*TK*2 bytes (fp16)
#define B_STAGE 32768   // TN*TK*2 bytes (fp16)
#define STAGE_BYTES 49152
#define NSTAGE 3
#define SMEM_DYN 148480 // 3*49152 + 1024 alignment slack

// Pre-swizzled, tile-ordered operand images (scratch via __device__ globals).
__device__ __align__(1024) uint8_t g_A[(size_t)M_TILES * K_ITERS * A_STAGE]; // 64 MB
__device__ __align__(1024) uint8_t g_B[(size_t)N_TILES * 64 * B_STAGE];      // 32 MB

// ---------------- helpers ----------------
static __device__ __forceinline__ uint32_t smem_u32(const void* p) {
    uint32_t a;
    asm("{ .reg .u64 t; cvta.to.shared.u64 t, %1; cvt.u32.u64 %0, t; }"
        : "=r"(a) : "l"(p));
    return a;
}

static __device__ __forceinline__ void cp16(uint32_t dst, const void* src) {
    asm volatile("cp.async.cg.shared.global [%0], [%1], 16;"
                 :: "r"(dst), "l"(src) : "memory");
}

static __device__ __forceinline__ void ldsm4(uint32_t (&r)[4], uint32_t addr) {
    asm volatile("ldmatrix.sync.aligned.m8n8.x4.shared.b16 {%0,%1,%2,%3}, [%4];"
                 : "=r"(r[0]), "=r"(r[1]), "=r"(r[2]), "=r"(r[3]) : "r"(addr));
}

static __device__ __forceinline__ void mma16816(float* d, const uint32_t* a,
                                                uint32_t b0, uint32_t b1) {
    asm volatile(
        "mma.sync.aligned.m16n8k16.row.col.f32.f16.f16.f32 "
        "{%0,%1,%2,%3}, {%4,%5,%6,%7}, {%8,%9}, {%0,%1,%2,%3};"
        : "+f"(d[0]), "+f"(d[1]), "+f"(d[2]), "+f"(d[3])
        : "r"(a[0]), "r"(a[1]), "r"(a[2]), "r"(a[3]), "r"(b0), "r"(b1));
}

// ============================================================================
// Prep X: fp32 X -> single fp16 image, pre-swizzled & tile-ordered.
// One thread = 8 consecutive K elements (one 16B swizzle chunk).
// ============================================================================
__global__ void prep_x_kernel(const float* __restrict__ X) {
    int g  = blockIdx.x * 256 + threadIdx.x;   // 8192*512 chunks
    int n  = g >> 9;
    int k0 = (g & 511) << 3;
    const float4* xp = reinterpret_cast<const float4*>(X + (size_t)n * D_IN + k0);
    float4 a = xp[0], b = xp[1];
    union { __half h[8]; uint4 u; } hi;
    hi.h[0] = __float2half_rn(a.x); hi.h[1] = __float2half_rn(a.y);
    hi.h[2] = __float2half_rn(a.z); hi.h[3] = __float2half_rn(a.w);
    hi.h[4] = __float2half_rn(b.x); hi.h[5] = __float2half_rn(b.y);
    hi.h[6] = __float2half_rn(b.z); hi.h[7] = __float2half_rn(b.w);
    int mt = n >> 7, m = n & 127, ks = k0 >> 6, kk = k0 & 63;
    uint32_t off = (uint32_t)(m * 128 + kk * 2);
    uint32_t sw  = off ^ ((off >> 3) & 0x70u);
    *reinterpret_cast<uint4*>(g_A + (size_t)(mt * 64 + ks) * A_STAGE + sw) = hi.u;
}

// ============================================================================
// Prep W: W' = (W_nf4 * c1) * c_kbit2 + L1@L2, transposed to N-major [d][k],
// fp16, pre-swizzled & tile-ordered. Block tile: 64 k x 32 d.
// ============================================================================
__global__ void prep_w_kernel(const float* __restrict__ Wn, const float* __restrict__ c1p,
                              const float* __restrict__ ck, const float* __restrict__ L1,
                              const float* __restrict__ L2) {
    __shared__ float sL1[64 * 16];
    __shared__ float sL2[16 * 32];
    __shared__ __align__(16) __half sOut[32 * 64];
    const int t  = threadIdx.x;
    const int k0 = blockIdx.y * 64;
    const int d0 = blockIdx.x * 32;
    const float c1 = __ldg(c1p);

    for (int i = t; i < 1024; i += 256) sL1[i] = L1[(size_t)k0 * 16 + i];
    for (int i = t; i < 512;  i += 256) sL2[i] = L2[(size_t)(i >> 5) * D_OUT + d0 + (i & 31)];

    const int dd = t & 31;
    float wv[8];
#pragma unroll
    for (int i = 0; i < 8; i++) {
        int k = (t >> 5) + i * 8;
        size_t gi = (size_t)(k0 + k) * D_OUT + d0 + dd;
        wv[i] = (Wn[gi] * c1) * ck[gi];   // match reference mul order
    }
    __syncthreads();
#pragma unroll
    for (int i = 0; i < 8; i++) {
        int k = (t >> 5) + i * 8;
        float acc = wv[i];
#pragma unroll
        for (int r = 0; r < 16; r++) acc += sL1[k * 16 + r] * sL2[r * 32 + dd];
        sOut[dd * 64 + k] = __float2half_rn(acc);
    }
    __syncthreads();
    const int od = t >> 3, c = t & 7;
    uint4 v = *reinterpret_cast<uint4*>(&sOut[od * 64 + c * 8]);
    int ntile = blockIdx.x >> 3;
    int nloc  = ((blockIdx.x & 7) << 5) + od;
    uint32_t off = (uint32_t)(nloc * 128 + c * 16);
    uint32_t sw  = off ^ ((off >> 3) & 0x70u);
    *reinterpret_cast<uint4*>(g_B + (size_t)(ntile * 64 + blockIdx.y) * B_STAGE + sw) = v;
}

// ============================================================================
// GEMM: Y[8192,4096] = Xh @ W' via mma.sync.m16n8k16 (HMMA).
// CTA tile 128x256, warp grid 2(m)x4(n) of 64x64 warp tiles.
// K-stage 64, 3-stage cp.async pipeline, ONE __syncthreads per K-iter
// (CUTLASS multistage pattern: refill buffer read last iteration).
// ============================================================================
static __device__ __forceinline__ void load_stage(uint32_t sA, uint32_t sB,
                                                  const uint8_t* gA, const uint8_t* gB,
                                                  int tid) {
#pragma unroll
    for (int i = 0; i < 4; i++) {
        uint32_t o = (uint32_t)(tid + i * 256) * 16u;
        cp16(sA + o, gA + o);
    }
#pragma unroll
    for (int i = 0; i < 8; i++) {
        uint32_t o = (uint32_t)(tid + i * 256) * 16u;
        cp16(sB + o, gB + o);
    }
}

__global__ void __launch_bounds__(256, 1) qlora_gemm(float* __restrict__ Y) {
    extern __shared__ __align__(16) uint8_t smem[];
    const int tid  = threadIdx.x;
    const int wid  = tid >> 5;
    const int lane = tid & 31;
    const int nt = blockIdx.x;     // n-tile fastest -> W' stays L2-resident
    const int mt = blockIdx.y;

    const int wm = wid >> 2;       // 0..1
    const int wn = wid & 3;        // 0..3

    uint32_t base   = smem_u32(smem);
    uint32_t stage0 = (base + 1023u) & ~1023u;

    // Per-lane ldmatrix addressing invariants.
    // SW128 within a 128B-row tile reduces to: addr = row*128 + (kb ^ ((row&7)*16)).
    const int lr = lane & 15;              // row within 16-row fragment group
    const int lk = (lane >> 4) * 16;       // +8 halves for upper 16 lanes
    const int xm = (lr & 7) * 16;
    uint32_t aRowOff[4], bRowOff[4];
#pragma unroll
    for (int mi = 0; mi < 4; mi++) aRowOff[mi] = (uint32_t)((wm * 64 + mi * 16 + lr) * 128);
#pragma unroll
    for (int nj = 0; nj < 4; nj++) bRowOff[nj] = (uint32_t)((wn * 64 + nj * 16 + lr) * 128);

    float acc[4][8][4];
#pragma unroll
    for (int mi = 0; mi < 4; mi++)
#pragma unroll
        for (int nj = 0; nj < 8; nj++)
#pragma unroll
            for (int c = 0; c < 4; c++) acc[mi][nj][c] = 0.0f;

    // prologue: fill NSTAGE-1 = 2 stages
#pragma unroll
    for (int s = 0; s < NSTAGE - 1; s++) {
        const uint8_t* gA = g_A + (size_t)(mt * 64 + s) * A_STAGE;
        const uint8_t* gB = g_B + (size_t)(nt * 64 + s) * B_STAGE;
        uint32_t sA = stage0 + s * STAGE_BYTES;
        load_stage(sA, sA + A_STAGE, gA, gB, tid);
        asm volatile("cp.async.commit_group;" ::: "memory");
    }

    int rbuf = 0, wbuf = NSTAGE - 1;
    for (int it = 0; it < K_ITERS; ++it) {
        uint32_t sA = stage0 + rbuf * STAGE_BYTES;
        uint32_t sB = sA + A_STAGE;
        asm volatile("cp.async.wait_group %0;" :: "n"(NSTAGE - 2) : "memory");
        __syncthreads();   // read-stage data visible to all; write-stage free

        // refill: stage it+NSTAGE-1 into wbuf (the buffer read at iter it-1)
        int nx = it + NSTAGE - 1;
        if (nx < K_ITERS) {
            const uint8_t* gA = g_A + (size_t)(mt * 64 + nx) * A_STAGE;
            const uint8_t* gB = g_B + (size_t)(nt * 64 + nx) * B_STAGE;
            uint32_t wA = stage0 + wbuf * STAGE_BYTES;
            load_stage(wA, wA + A_STAGE, gA, gB, tid);
        }
        asm volatile("cp.async.commit_group;" ::: "memory");

#pragma unroll
        for (int ks = 0; ks < 4; ks++) {
            uint32_t kb = (uint32_t)((ks * 32 + lk) ^ xm);
            uint32_t a[4][4], bq[4][4];
#pragma unroll
            for (int mi = 0; mi < 4; mi++) ldsm4(a[mi],  sA + aRowOff[mi] + kb);
#pragma unroll
            for (int nj = 0; nj < 4; nj++) ldsm4(bq[nj], sB + bRowOff[nj] + kb);
#pragma unroll
            for (int mi = 0; mi < 4; mi++)
#pragma unroll
                for (int nj = 0; nj < 4; nj++) {
                    mma16816(acc[mi][2 * nj],     a[mi], bq[nj][0], bq[nj][2]);
                    mma16816(acc[mi][2 * nj + 1], a[mi], bq[nj][1], bq[nj][3]);
                }
        }

        wbuf = rbuf;
        rbuf++; if (rbuf == NSTAGE) rbuf = 0;
    }

    // epilogue: direct fp32 stores (float2, 32B-sector aligned per lane quad)
    float* yBase = Y + (size_t)(mt * 128 + wm * 64) * D_OUT + nt * 256 + wn * 64;
    const int qr = lane >> 2;          // 0..7
    const int qc = (lane & 3) * 2;
#pragma unroll
    for (int mi = 0; mi < 4; mi++) {
        float* y0 = yBase + (size_t)(mi * 16 + qr) * D_OUT + qc;
        float* y1 = y0 + (size_t)8 * D_OUT;
#pragma unroll
        for (int nj = 0; nj < 8; nj++) {
            *reinterpret_cast<float2*>(y0 + nj * 8) = make_float2(acc[mi][nj][0], acc[mi][nj][1]);
            *reinterpret_cast<float2*>(y1 + nj * 8) = make_float2(acc[mi][nj][2], acc[mi][nj][3]);
        }
    }
}

// ============================================================================
extern "C" void kernel_launch(void* const* d_in, const int* in_sizes, int n_in,
                              void* d_out, int out_size) {
    (void)in_sizes; (void)n_in; (void)out_size;
    const float* X  = (const float*)d_in[0];
    const float* Wn = (const float*)d_in[1];
    const float* c1 = (const float*)d_in[2];
    const float* ck = (const float*)d_in[3];
    const float* L1 = (const float*)d_in[4];
    const float* L2 = (const float*)d_in[5];
    float* Y = (float*)d_out;

    prep_x_kernel<<<16384, 256>>>(X);
    prep_w_kernel<<<dim3(128, 64), 256>>>(Wn, c1, ck, L1, L2);
    cudaFuncSetAttribute(qlora_gemm, cudaFuncAttributeMaxDynamicSharedMemorySize, SMEM_DYN);
    qlora_gemm<<<dim3(N_TILES, M_TILES), 256, SMEM_DYN>>>(Y);
}